// round 1
// baseline (speedup 1.0000x reference)
#include <cuda_runtime.h>
#include <math.h>

#define NQ 8
#define BATCHN 8192
#define INDIM 512
#define PI_F 3.14159265358979323846f

__device__ __forceinline__ float2 shx(float2 v, int m) {
    v.x = __shfl_xor_sync(0xffffffffu, v.x, m);
    v.y = __shfl_xor_sync(0xffffffffu, v.y, m);
    return v;
}
__device__ __forceinline__ float2 cmul(float2 a, float2 b) {
    return make_float2(a.x * b.x - a.y * b.y, a.x * b.y + a.y * b.x);
}
// a*b + c
__device__ __forceinline__ float2 cfma(float2 a, float2 b, float2 c) {
    float2 r;
    r.x = fmaf(a.x, b.x, fmaf(-a.y, b.y, c.x));
    r.y = fmaf(a.x, b.y, fmaf(a.y, b.x, c.y));
    return r;
}

// 1-qubit gate on amplitude-bit Q (bit = 7 - wire). Lane holds bits [7:3], k holds [2:0].
template<int Q>
__device__ __forceinline__ void gate1(float2 s[8], float2 u00, float2 u01, float2 u10, float2 u11,
                                      unsigned lane) {
    if (Q < 3) {
        constexpr int m = 1 << ((Q < 3) ? Q : 0);
        #pragma unroll
        for (int k = 0; k < 8; k++) {
            if (!(k & m)) {
                float2 a = s[k], b = s[k | m];
                s[k]     = cfma(u00, a, cmul(u01, b));
                s[k | m] = cfma(u10, a, cmul(u11, b));
            }
        }
    } else {
        constexpr int sh = (Q >= 3) ? (Q - 3) : 0;
        constexpr int lm = 1 << sh;
        int bit = (lane >> sh) & 1;
        float2 cm_ = bit ? u11 : u00;   // coefficient of my amplitude
        float2 co_ = bit ? u10 : u01;   // coefficient of partner amplitude
        #pragma unroll
        for (int k = 0; k < 8; k++) {
            float2 o = shx(s[k], lm);
            s[k] = cfma(cm_, s[k], cmul(co_, o));
        }
    }
}

// CNOT with control bit CB, target bit TB (amplitude-bit space)
template<int CB, int TB>
__device__ __forceinline__ void cnotg(float2 s[8], unsigned lane) {
    if (CB < 3 && TB < 3) {
        constexpr int cm = 1 << ((CB < 3) ? CB : 0);
        constexpr int tm = 1 << ((TB < 3) ? TB : 0);
        #pragma unroll
        for (int k = 0; k < 8; k++) {
            if ((k & cm) && !(k & tm)) {
                float2 t = s[k]; s[k] = s[k | tm]; s[k | tm] = t;
            }
        }
    } else if (CB < 3 && TB >= 3) {
        constexpr int cm = 1 << ((CB < 3) ? CB : 0);
        constexpr int lm = 1 << ((TB >= 3) ? (TB - 3) : 0);
        #pragma unroll
        for (int k = 0; k < 8; k++) {
            if (k & cm) s[k] = shx(s[k], lm);
        }
    } else if (CB >= 3 && TB < 3) {
        constexpr int tm = 1 << ((TB < 3) ? TB : 0);
        constexpr int cs = (CB >= 3) ? (CB - 3) : 0;
        int cb = (lane >> cs) & 1;
        #pragma unroll
        for (int k = 0; k < 8; k++) {
            if (!(k & tm)) {
                float2 a = s[k], b = s[k | tm];
                s[k].x      = cb ? b.x : a.x;  s[k].y      = cb ? b.y : a.y;
                s[k | tm].x = cb ? a.x : b.x;  s[k | tm].y = cb ? a.y : b.y;
            }
        }
    } else {
        constexpr int lm = 1 << ((TB >= 3) ? (TB - 3) : 0);
        constexpr int cs = (CB >= 3) ? (CB - 3) : 0;
        int cb = (lane >> cs) & 1;
        #pragma unroll
        for (int k = 0; k < 8; k++) {
            float2 o = shx(s[k], lm);
            s[k].x = cb ? o.x : s[k].x;
            s[k].y = cb ? o.y : s[k].y;
        }
    }
}

__global__ __launch_bounds__(256) void qlayer_kernel(
    const float* __restrict__ x,
    const float* __restrict__ W,
    const float* __restrict__ bvec,
    const float* __restrict__ scale,
    const float* __restrict__ bias,
    const float* __restrict__ qw,
    float* __restrict__ out)
{
    __shared__ float sW[8][512];           // 16 KB
    __shared__ float2 sG[3][8][4];         // Rot matrices per layer/wire
    __shared__ unsigned char sP[256];      // permutation of final CNOT ring (r=3)

    const int tid = threadIdx.x;

    // ---- block-level precompute ----
    for (int i = tid; i < 8 * 512; i += 256) ((float*)sW)[i] = W[i];

    if (tid < 24) {
        int l = tid / 8, w = tid % 8;
        float phi = qw[(l * 8 + w) * 3 + 0];
        float th  = qw[(l * 8 + w) * 3 + 1];
        float om  = qw[(l * 8 + w) * 3 + 2];
        float ct, st_;
        sincosf(0.5f * th, &st_, &ct);
        float a0 = 0.5f * (phi + om);
        float a1 = 0.5f * (phi - om);
        float c0, s0, c1, s1;
        sincosf(a0, &s0, &c0);
        sincosf(a1, &s1, &c1);
        sG[l][w][0] = make_float2( ct * c0, -ct * s0);   // u00 = e^{-i a0} c
        sG[l][w][1] = make_float2(-st_ * c1, -st_ * s1); // u01 = -e^{+i a1} s
        sG[l][w][2] = make_float2( st_ * c1, -st_ * s1); // u10 = e^{-i a1} s
        sG[l][w][3] = make_float2( ct * c0,  ct * s0);   // u11 = e^{+i a0} c
    }
    if (tid < 256) {
        // final ring r=3: track where amplitude i ends up
        int j = tid;
        #pragma unroll
        for (int w = 0; w < 8; w++) {
            int c = 7 - w;
            int t = 7 - ((w + 3) & 7);
            if ((j >> c) & 1) j ^= (1 << t);
        }
        sP[tid] = (unsigned char)j;
    }
    __syncthreads();

    const unsigned lane = tid & 31;
    const int b = blockIdx.x * 8 + (tid >> 5);
    if (b >= BATCHN) return;

    // ---- projection: proj[w] = x[b] . W[w] ----
    float acc[8];
    #pragma unroll
    for (int w = 0; w < 8; w++) acc[w] = 0.f;
    const float4* xr = (const float4*)(x + (size_t)b * INDIM);
    #pragma unroll
    for (int c = 0; c < 4; c++) {
        float4 xv = xr[c * 32 + lane];
        #pragma unroll
        for (int w = 0; w < 8; w++) {
            float4 wv = ((const float4*)(sW[w]))[c * 32 + lane];
            acc[w] += xv.x * wv.x + xv.y * wv.y + xv.z * wv.z + xv.w * wv.w;
        }
    }
    #pragma unroll
    for (int off = 16; off > 0; off >>= 1) {
        #pragma unroll
        for (int w = 0; w < 8; w++) acc[w] += __shfl_xor_sync(0xffffffffu, acc[w], off);
    }

    // ---- angles + fold layer-0 Rot into per-wire 2-vectors ----
    float2 wa[8], wb[8];
    #pragma unroll
    for (int w = 0; w < 8; w++) {
        float p = acc[w] + __ldg(&bvec[w]);
        float t = p * __ldg(&scale[w]) + __ldg(&bias[w]);
        float sg = 1.f / (1.f + expf(-t));
        float half = sg * (0.5f * PI_F);
        float cc, ss;
        sincosf(half, &ss, &cc);                  // v_w = (cc, ss), real
        float2 g00 = sG[0][w][0], g01 = sG[0][w][1];
        float2 g10 = sG[0][w][2], g11 = sG[0][w][3];
        wa[w] = make_float2(fmaf(g00.x, cc, g01.x * ss), fmaf(g00.y, cc, g01.y * ss));
        wb[w] = make_float2(fmaf(g10.x, cc, g11.x * ss), fmaf(g10.y, cc, g11.y * ss));
    }

    // ---- build product state: bit p <-> wire 7-p; i = (lane<<3)|k ----
    float2 A = (lane & 1)  ? wb[4] : wa[4];
    A = cmul(A, (lane & 2)  ? wb[3] : wa[3]);
    A = cmul(A, (lane & 4)  ? wb[2] : wa[2]);
    A = cmul(A, (lane & 8)  ? wb[1] : wa[1]);
    A = cmul(A, (lane & 16) ? wb[0] : wa[0]);

    float2 s[8];
    #pragma unroll
    for (int k = 0; k < 8; k++) {
        float2 Bv = cmul((k & 1) ? wb[7] : wa[7], (k & 2) ? wb[6] : wa[6]);
        Bv = cmul(Bv, (k & 4) ? wb[5] : wa[5]);
        s[k] = cmul(A, Bv);
    }

    // ---- CNOT ring r=1 (layer 0) ----
    cnotg<7, 6>(s, lane);
    cnotg<6, 5>(s, lane);
    cnotg<5, 4>(s, lane);
    cnotg<4, 3>(s, lane);
    cnotg<3, 2>(s, lane);
    cnotg<2, 1>(s, lane);
    cnotg<1, 0>(s, lane);
    cnotg<0, 7>(s, lane);

    // ---- layer-1 Rots (wire w -> bit 7-w) ----
    #define G1(w, B) gate1<B>(s, sG[1][w][0], sG[1][w][1], sG[1][w][2], sG[1][w][3], lane)
    G1(0, 7); G1(1, 6); G1(2, 5); G1(3, 4); G1(4, 3); G1(5, 2); G1(6, 1); G1(7, 0);
    #undef G1

    // ---- CNOT ring r=2 ----
    cnotg<7, 5>(s, lane);
    cnotg<6, 4>(s, lane);
    cnotg<5, 3>(s, lane);
    cnotg<4, 2>(s, lane);
    cnotg<3, 1>(s, lane);
    cnotg<2, 0>(s, lane);
    cnotg<1, 7>(s, lane);
    cnotg<0, 6>(s, lane);

    // ---- layer-2 Rots ----
    #define G2(w, B) gate1<B>(s, sG[2][w][0], sG[2][w][1], sG[2][w][2], sG[2][w][3], lane)
    G2(0, 7); G2(1, 6); G2(2, 5); G2(3, 4); G2(4, 3); G2(5, 2); G2(6, 1); G2(7, 0);
    #undef G2

    // ---- measurement: ring r=3 folded into sign masks via sP ----
    float z[8];
    #pragma unroll
    for (int w = 0; w < 8; w++) z[w] = 0.f;
    #pragma unroll
    for (int k = 0; k < 8; k++) {
        float p = s[k].x * s[k].x + s[k].y * s[k].y;
        int j = (int)sP[(lane << 3) | k];
        #pragma unroll
        for (int w = 0; w < 8; w++) {
            // z_w uses bit (7-w) of the permuted index: sign bit = j<<(24+w) & 0x80000000
            int sm = (j << (24 + w)) & 0x80000000;
            z[w] += __int_as_float(__float_as_int(p) ^ sm);
        }
    }
    #pragma unroll
    for (int off = 16; off > 0; off >>= 1) {
        #pragma unroll
        for (int w = 0; w < 8; w++) z[w] += __shfl_xor_sync(0xffffffffu, z[w], off);
    }

    if (lane < 8) {
        float v = z[0];
        if (lane == 1) v = z[1];
        if (lane == 2) v = z[2];
        if (lane == 3) v = z[3];
        if (lane == 4) v = z[4];
        if (lane == 5) v = z[5];
        if (lane == 6) v = z[6];
        if (lane == 7) v = z[7];
        out[(size_t)b * 8 + lane] = v;
    }
}

extern "C" void kernel_launch(void* const* d_in, const int* in_sizes, int n_in,
                              void* d_out, int out_size) {
    const float* x     = (const float*)d_in[0];
    const float* W     = (const float*)d_in[1];
    const float* bvec  = (const float*)d_in[2];
    const float* scale = (const float*)d_in[3];
    const float* bias  = (const float*)d_in[4];
    const float* qw    = (const float*)d_in[5];
    float* out = (float*)d_out;
    qlayer_kernel<<<BATCHN / 8, 256>>>(x, W, bvec, scale, bias, qw, out);
}

// round 4
// speedup vs baseline: 1.1221x; 1.1221x over previous
#include <cuda_runtime.h>
#include <math.h>

typedef unsigned long long ull;
#define BATCHN 8192
#define INDIM 512
#define PI_F 3.14159265358979323846f

// ---------- f32x2 packed primitives ----------
__device__ __forceinline__ ull pk(float x, float y) {
    ull r; asm("mov.b64 %0, {%1, %2};" : "=l"(r) : "f"(x), "f"(y)); return r;
}
__device__ __forceinline__ float2 upk(ull v) {
    float2 f; asm("mov.b64 {%0, %1}, %2;" : "=f"(f.x), "=f"(f.y) : "l"(v)); return f;
}
__device__ __forceinline__ ull spl(float x) { return pk(x, x); }
__device__ __forceinline__ ull f2fma(ull a, ull b, ull c) {
    ull d; asm("fma.rn.f32x2 %0, %1, %2, %3;" : "=l"(d) : "l"(a), "l"(b), "l"(c)); return d;
}
__device__ __forceinline__ ull f2mul(ull a, ull b) {
    ull d; asm("mul.rn.f32x2 %0, %1, %2;" : "=l"(d) : "l"(a), "l"(b)); return d;
}
__device__ __forceinline__ ull f2add(ull a, ull b) {
    ull d; asm("add.rn.f32x2 %0, %1, %2;" : "=l"(d) : "l"(a), "l"(b)); return d;
}
__device__ __forceinline__ ull shx64(ull v, int m) {
    float2 f = upk(v);
    f.x = __shfl_xor_sync(0xffffffffu, f.x, m);
    f.y = __shfl_xor_sync(0xffffffffu, f.y, m);
    return pk(f.x, f.y);
}
__device__ __forceinline__ float2 cmul(float2 a, float2 b) {
    return make_float2(a.x * b.x - a.y * b.y, a.x * b.y + a.y * b.x);
}

// splatted coefficient sets (each ull = (v,v))
struct __align__(16) GateSplats { ull u00r, u00i, nu00i, u01r, nu01r, u01i, nu01i, pad; };
struct __align__(16) VSplats   { ull v00r, v00i, nv00i, v01r, v01i, nv01i, p0, p1; };

// ---------- gates on packed state: R[j]/I[j] hold amps (2j, 2j+1) ----------
// amp index i = (lane<<3) | (2j + h);  bit0 = h (pack half), bits1-2 = j, bits3-7 = lane

// single-qubit gate on a lane bit (CS = lane-bit index, amp bit CS+3)
template<int CS>
__device__ __forceinline__ void gate_shfl(ull R[4], ull I[4], unsigned lane, const GateSplats* gp) {
    const ulonglong2* q = reinterpret_cast<const ulonglong2*>(gp);
    ulonglong2 q0 = q[0], q1 = q[1], q2 = q[2], q3 = q[3];
    ull u00r = q0.x, u00i = q0.y, nu00i = q1.x, u01r = q1.y;
    ull nu01r = q2.x, u01i = q2.y, nu01i = q3.x;
    bool bit = (lane >> CS) & 1;
    // cm = bit ? u11 : u00 (u11 = conj(u00)); co = bit ? u10 : u01 (u10 = (-u01.re, u01.im))
    ull CMr  = u00r;
    ull CMi  = bit ? nu00i : u00i;
    ull nCMi = bit ? u00i  : nu00i;
    ull COr  = bit ? nu01r : u01r;
    ull COi  = u01i, nCOi = nu01i;
    #pragma unroll
    for (int j = 0; j < 4; j++) {
        ull oR = shx64(R[j], 1 << CS), oI = shx64(I[j], 1 << CS);
        ull sR = R[j], sI = I[j];
        R[j] = f2fma(CMr, sR, f2fma(nCMi, sI, f2fma(COr, oR, f2mul(nCOi, oI))));
        I[j] = f2fma(CMr, sI, f2fma(CMi, sR, f2fma(COr, oI, f2mul(COi, oR))));
    }
}

// single-qubit gate on a pack bit (PM = 1 or 2)
template<int PM>
__device__ __forceinline__ void gate_cross(ull R[4], ull I[4], const GateSplats* gp) {
    const ulonglong2* q = reinterpret_cast<const ulonglong2*>(gp);
    ulonglong2 q0 = q[0], q1 = q[1], q2 = q[2], q3 = q[3];
    ull u00r = q0.x, u00i = q0.y, nu00i = q1.x, u01r = q1.y;
    ull nu01r = q2.x, u01i = q2.y, nu01i = q3.x;
    #pragma unroll
    for (int j = 0; j < 4; j++) {
        if (!(j & PM)) {
            ull aR = R[j], aI = I[j], bR = R[j | PM], bI = I[j | PM];
            R[j]      = f2fma(u00r,  aR, f2fma(nu00i, aI, f2fma(u01r, bR, f2mul(nu01i, bI))));
            I[j]      = f2fma(u00r,  aI, f2fma(u00i,  aR, f2fma(u01r, bI, f2mul(u01i,  bR))));
            R[j | PM] = f2fma(nu01r, aR, f2fma(nu01i, aI, f2fma(u00r, bR, f2mul(u00i,  bI))));
            I[j | PM] = f2fma(nu01r, aI, f2fma(u01i,  aR, f2fma(u00r, bI, f2mul(nu00i, bR))));
        }
    }
}

// single-qubit gate on the pack-half bit (amp bit 0)
__device__ __forceinline__ void gate_v(ull R[4], ull I[4], const VSplats* vp) {
    const ulonglong2* q = reinterpret_cast<const ulonglong2*>(vp);
    ulonglong2 q0 = q[0], q1 = q[1], q2 = q[2];
    ull v00r = q0.x, v00i = q0.y, nv00i = q1.x, v01r = q1.y, v01i = q2.x, nv01i = q2.y;
    #pragma unroll
    for (int j = 0; j < 4; j++) {
        float2 fr = upk(R[j]), fi = upk(I[j]);
        ull aRe = spl(fr.x), bRe = spl(fr.y), aIm = spl(fi.x), bIm = spl(fi.y);
        R[j] = f2fma(v00r, aRe, f2fma(nv00i, aIm, f2fma(v01r, bRe, f2mul(nv01i, bIm))));
        I[j] = f2fma(v00r, aIm, f2fma(v00i,  aRe, f2fma(v01r, bIm, f2mul(v01i,  bRe))));
    }
}

// ---------- CNOTs ----------
// control lane bit CS, target lane bit (mask LM)
template<int CS, int LM>
__device__ __forceinline__ void cnot_ll(ull R[4], ull I[4], unsigned lane) {
    bool cb = (lane >> CS) & 1;
    #pragma unroll
    for (int j = 0; j < 4; j++) {
        ull o = shx64(R[j], LM); R[j] = cb ? o : R[j];
        o = shx64(I[j], LM);     I[j] = cb ? o : I[j];
    }
}
// control lane bit CS, target pack bit PM
template<int CS, int PM>
__device__ __forceinline__ void cnot_lp(ull R[4], ull I[4], unsigned lane) {
    bool cb = (lane >> CS) & 1;
    #pragma unroll
    for (int j = 0; j < 4; j++) {
        if (!(j & PM)) {
            ull a = R[j], b = R[j | PM];
            R[j] = cb ? b : a; R[j | PM] = cb ? a : b;
            a = I[j]; b = I[j | PM];
            I[j] = cb ? b : a; I[j | PM] = cb ? a : b;
        }
    }
}
// control pack bit PM, target = half bit: swap halves of packs with j&PM
template<int PM>
__device__ __forceinline__ void cnot_ph(ull R[4], ull I[4]) {
    #pragma unroll
    for (int j = 0; j < 4; j++) {
        if (j & PM) {
            float2 r = upk(R[j]); R[j] = pk(r.y, r.x);
            float2 i = upk(I[j]); I[j] = pk(i.y, i.x);
        }
    }
}
// control pack bit PM, target lane bit: full exchange of packs with j&PM
template<int PM, int LM>
__device__ __forceinline__ void cnot_pl(ull R[4], ull I[4]) {
    #pragma unroll
    for (int j = 0; j < 4; j++) {
        if (j & PM) { R[j] = shx64(R[j], LM); I[j] = shx64(I[j], LM); }
    }
}
// control = half bit (hi halves), target lane bit: shfl only hi halves
template<int LM>
__device__ __forceinline__ void cnot_hl(ull R[4], ull I[4]) {
    #pragma unroll
    for (int j = 0; j < 4; j++) {
        float2 r = upk(R[j]);
        r.y = __shfl_xor_sync(0xffffffffu, r.y, LM);
        R[j] = pk(r.x, r.y);
        float2 i = upk(I[j]);
        i.y = __shfl_xor_sync(0xffffffffu, i.y, LM);
        I[j] = pk(i.x, i.y);
    }
}

__global__ __launch_bounds__(256) void qlayer_kernel(
    const float* __restrict__ x,
    const float* __restrict__ W,
    const float* __restrict__ bvec,
    const float* __restrict__ scale,
    const float* __restrict__ bias,
    const float* __restrict__ qw,
    float* __restrict__ out)
{
    __shared__ float sW[8][512];          // 16 KB
    __shared__ GateSplats sSp[2][8];      // layers 1,2 splatted Rot coeffs
    __shared__ VSplats sV[2];             // layers 1,2 wire-7 (bit0) coeffs
    __shared__ float2 sG0[8][4];          // layer 0 raw Rot matrices
    __shared__ unsigned char sP[256];     // final-ring permutation

    const int tid = threadIdx.x;

    for (int i = tid; i < 1024; i += 256)
        ((float4*)sW)[i] = ((const float4*)W)[i];

    if (tid < 24) {
        int l = tid >> 3, w = tid & 7;
        const float* qp = qw + (l * 8 + w) * 3;
        float phi = qp[0], th = qp[1], om = qp[2];
        float ct, st_; sincosf(0.5f * th, &st_, &ct);
        float c0, s0, c1, s1;
        sincosf(0.5f * (phi + om), &s0, &c0);
        sincosf(0.5f * (phi - om), &s1, &c1);
        float2 u00 = make_float2(ct * c0, -ct * s0);
        float2 u01 = make_float2(-st_ * c1, -st_ * s1);
        if (l == 0) {
            sG0[w][0] = u00;
            sG0[w][1] = u01;
            sG0[w][2] = make_float2(st_ * c1, -st_ * s1);  // u10
            sG0[w][3] = make_float2(ct * c0, ct * s0);     // u11
        } else {
            GateSplats& g = sSp[l - 1][w];
            g.u00r = spl(u00.x); g.u00i = spl(u00.y); g.nu00i = spl(-u00.y);
            g.u01r = spl(u01.x); g.nu01r = spl(-u01.x);
            g.u01i = spl(u01.y); g.nu01i = spl(-u01.y);
            g.pad = 0;
            if (w == 7) {
                float2 u10 = make_float2(-u01.x, u01.y);
                float2 u11 = make_float2(u00.x, -u00.y);
                VSplats& v = sV[l - 1];
                v.v00r = pk(u00.x, u10.x); v.v00i = pk(u00.y, u10.y); v.nv00i = pk(-u00.y, -u10.y);
                v.v01r = pk(u01.x, u11.x); v.v01i = pk(u01.y, u11.y); v.nv01i = pk(-u01.y, -u11.y);
                v.p0 = 0; v.p1 = 0;
            }
        }
    }
    {
        // final CNOT ring r=3 as an index permutation (linear over GF(2))
        int j = tid;
        #pragma unroll
        for (int w = 0; w < 8; w++) {
            int c = 7 - w, t = 7 - ((w + 3) & 7);
            if ((j >> c) & 1) j ^= (1 << t);
        }
        sP[tid] = (unsigned char)j;
    }
    __syncthreads();

    const unsigned lane = tid & 31;
    const int b = blockIdx.x * 8 + (tid >> 5);

    // ---- projection: proj[w] = x[b] . W[w] ----
    float acc[8];
    #pragma unroll
    for (int w = 0; w < 8; w++) acc[w] = 0.f;
    const float4* xr = (const float4*)(x + (size_t)b * INDIM);
    #pragma unroll
    for (int c = 0; c < 4; c++) {
        float4 xv = xr[c * 32 + lane];
        #pragma unroll
        for (int w = 0; w < 8; w++) {
            float4 wv = ((const float4*)(sW[w]))[c * 32 + lane];
            acc[w] += xv.x * wv.x + xv.y * wv.y + xv.z * wv.z + xv.w * wv.w;
        }
    }
    #pragma unroll
    for (int off = 16; off > 0; off >>= 1) {
        #pragma unroll
        for (int w = 0; w < 8; w++) acc[w] += __shfl_xor_sync(0xffffffffu, acc[w], off);
    }

    // ---- angles + fold layer-0 Rot into per-wire 2-vectors ----
    float2 wa[8], wb[8];
    #pragma unroll
    for (int w = 0; w < 8; w++) {
        float p = acc[w] + __ldg(&bvec[w]);
        float t = p * __ldg(&scale[w]) + __ldg(&bias[w]);
        float sg = 1.f / (1.f + __expf(-t));
        float half = sg * (0.5f * PI_F);
        float cc, ss;
        __sincosf(half, &ss, &cc);                 // RY(angle)|0> = (cc, ss), real
        float2 g00 = sG0[w][0], g01 = sG0[w][1];
        float2 g10 = sG0[w][2], g11 = sG0[w][3];
        wa[w] = make_float2(fmaf(g00.x, cc, g01.x * ss), fmaf(g00.y, cc, g01.y * ss));
        wb[w] = make_float2(fmaf(g10.x, cc, g11.x * ss), fmaf(g10.y, cc, g11.y * ss));
    }

    // ---- build packed product state ----
    float2 A = (lane & 1) ? wb[4] : wa[4];
    A = cmul(A, (lane & 2)  ? wb[3] : wa[3]);
    A = cmul(A, (lane & 4)  ? wb[2] : wa[2]);
    A = cmul(A, (lane & 8)  ? wb[1] : wa[1]);
    A = cmul(A, (lane & 16) ? wb[0] : wa[0]);

    float2 A6a = cmul(A, wa[6]), A6b = cmul(A, wb[6]);
    float2 C[4];
    C[0] = cmul(A6a, wa[5]); C[1] = cmul(A6b, wa[5]);
    C[2] = cmul(A6a, wb[5]); C[3] = cmul(A6b, wb[5]);

    ull W7r = pk(wa[7].x, wb[7].x);
    ull W7i = pk(wa[7].y, wb[7].y);
    ull nW7i = pk(-wa[7].y, -wb[7].y);

    ull R[4], I[4];
    #pragma unroll
    for (int j = 0; j < 4; j++) {
        ull Cre = spl(C[j].x), Cim = spl(C[j].y);
        R[j] = f2fma(Cre, W7r, f2mul(Cim, nW7i));
        I[j] = f2fma(Cre, W7i, f2mul(Cim, W7r));
    }

    // ---- CNOT ring r=1 : (CB,TB) = (7,6)(6,5)(5,4)(4,3)(3,2)(2,1)(1,0)(0,7) ----
    cnot_ll<4, 8>(R, I, lane);
    cnot_ll<3, 4>(R, I, lane);
    cnot_ll<2, 2>(R, I, lane);
    cnot_ll<1, 1>(R, I, lane);
    cnot_lp<0, 2>(R, I, lane);
    { ull t = R[2]; R[2] = R[3]; R[3] = t; t = I[2]; I[2] = I[3]; I[3] = t; }  // (2,1)
    cnot_ph<1>(R, I);                                                          // (1,0)
    cnot_hl<16>(R, I);                                                         // (0,7)

    // ---- layer-1 Rots (wire w -> amp bit 7-w) ----
    gate_shfl<4>(R, I, lane, &sSp[0][0]);
    gate_shfl<3>(R, I, lane, &sSp[0][1]);
    gate_shfl<2>(R, I, lane, &sSp[0][2]);
    gate_shfl<1>(R, I, lane, &sSp[0][3]);
    gate_shfl<0>(R, I, lane, &sSp[0][4]);
    gate_cross<2>(R, I, &sSp[0][5]);
    gate_cross<1>(R, I, &sSp[0][6]);
    gate_v(R, I, &sV[0]);

    // ---- CNOT ring r=2 : (7,5)(6,4)(5,3)(4,2)(3,1)(2,0)(1,7)(0,6) ----
    cnot_ll<4, 4>(R, I, lane);
    cnot_ll<3, 2>(R, I, lane);
    cnot_ll<2, 1>(R, I, lane);
    cnot_lp<1, 2>(R, I, lane);
    cnot_lp<0, 1>(R, I, lane);
    cnot_ph<2>(R, I);
    cnot_pl<1, 16>(R, I);
    cnot_hl<8>(R, I);

    // ---- layer-2 Rots ----
    gate_shfl<4>(R, I, lane, &sSp[1][0]);
    gate_shfl<3>(R, I, lane, &sSp[1][1]);
    gate_shfl<2>(R, I, lane, &sSp[1][2]);
    gate_shfl<1>(R, I, lane, &sSp[1][3]);
    gate_shfl<0>(R, I, lane, &sSp[1][4]);
    gate_cross<2>(R, I, &sSp[1][5]);
    gate_cross<1>(R, I, &sSp[1][6]);
    gate_v(R, I, &sV[1]);

    // ---- measurement: ring r=3 folded via sP; z_w = T - 2*sum_{bit set} p ----
    float p[8];
    #pragma unroll
    for (int j = 0; j < 4; j++) {
        ull P = f2fma(R[j], R[j], f2mul(I[j], I[j]));
        float2 pp = upk(P);
        p[2 * j] = pp.x; p[2 * j + 1] = pp.y;
    }
    float zs[8];
    #pragma unroll
    for (int w = 0; w < 8; w++) zs[w] = 0.f;
    float tot = 0.f;
    #pragma unroll
    for (int k = 0; k < 8; k++) {
        unsigned j8 = sP[(lane << 3) | k];
        tot += p[k];
        #pragma unroll
        for (int w = 0; w < 8; w++)
            zs[w] += ((j8 >> (7 - w)) & 1) ? p[k] : 0.f;
    }
    // packed warp reduction
    ull zp[4];
    #pragma unroll
    for (int t = 0; t < 4; t++) zp[t] = pk(zs[2 * t], zs[2 * t + 1]);
    #pragma unroll
    for (int off = 16; off > 0; off >>= 1) {
        #pragma unroll
        for (int t = 0; t < 4; t++) zp[t] = f2add(zp[t], shx64(zp[t], off));
        tot += __shfl_xor_sync(0xffffffffu, tot, off);
    }

    if (lane < 8) {
        float2 z0 = upk(zp[0]), z1 = upk(zp[1]), z2 = upk(zp[2]), z3 = upk(zp[3]);
        float v = z0.x;
        if (lane == 1) v = z0.y;
        if (lane == 2) v = z1.x;
        if (lane == 3) v = z1.y;
        if (lane == 4) v = z2.x;
        if (lane == 5) v = z2.y;
        if (lane == 6) v = z3.x;
        if (lane == 7) v = z3.y;
        out[(size_t)b * 8 + lane] = fmaf(-2.f, v, tot);
    }
}

extern "C" void kernel_launch(void* const* d_in, const int* in_sizes, int n_in,
                              void* d_out, int out_size) {
    const float* x     = (const float*)d_in[0];
    const float* W     = (const float*)d_in[1];
    const float* bvec  = (const float*)d_in[2];
    const float* scale = (const float*)d_in[3];
    const float* bias  = (const float*)d_in[4];
    const float* qw    = (const float*)d_in[5];
    float* out = (float*)d_out;
    qlayer_kernel<<<BATCHN / 8, 256>>>(x, W, bvec, scale, bias, qw, out);
}

// round 6
// speedup vs baseline: 1.3022x; 1.1606x over previous
#include <cuda_runtime.h>
#include <math.h>

typedef unsigned long long ull;
#define BATCHN 8192
#define INDIM 512
#define PI_F 3.14159265358979323846f

// ---------- f32x2 packed primitives ----------
__device__ __forceinline__ ull pk(float x, float y) {
    ull r; asm("mov.b64 %0, {%1, %2};" : "=l"(r) : "f"(x), "f"(y)); return r;
}
__device__ __forceinline__ float2 upk(ull v) {
    float2 f; asm("mov.b64 {%0, %1}, %2;" : "=f"(f.x), "=f"(f.y) : "l"(v)); return f;
}
__device__ __forceinline__ ull spl(float x) { return pk(x, x); }
__device__ __forceinline__ ull f2fma(ull a, ull b, ull c) {
    ull d; asm("fma.rn.f32x2 %0, %1, %2, %3;" : "=l"(d) : "l"(a), "l"(b), "l"(c)); return d;
}
__device__ __forceinline__ ull f2mul(ull a, ull b) {
    ull d; asm("mul.rn.f32x2 %0, %1, %2;" : "=l"(d) : "l"(a), "l"(b)); return d;
}
__device__ __forceinline__ ull f2add(ull a, ull b) {
    ull d; asm("add.rn.f32x2 %0, %1, %2;" : "=l"(d) : "l"(a), "l"(b)); return d;
}
__device__ __forceinline__ ull shx64(ull v, int m) {
    float2 f = upk(v);
    f.x = __shfl_xor_sync(0xffffffffu, f.x, m);
    f.y = __shfl_xor_sync(0xffffffffu, f.y, m);
    return pk(f.x, f.y);
}
__device__ __forceinline__ float2 cmul(float2 a, float2 b) {
    return make_float2(a.x * b.x - a.y * b.y, a.x * b.y + a.y * b.x);
}

struct __align__(16) GateSplats { ull u00r, u00i, nu00i, u01r, nu01r, u01i, nu01i, pad; };
struct __align__(16) VSplats   { ull v00r, v00i, nv00i, v01r, v01i, nv01i, p0, p1; };

// ======== layout ========
// warp = 4 batch elements; element e = lane>>3, octet-lane o = lane&7.
// amp index i[7:0]: bits[7:5] = o (o2=bit7,o1=bit6,o0=bit5), bits[4:1] = pack j
// (j3=bit4..j0=bit1), bit0 = pack half h. wire w <-> amp bit 7-w.
// wires 0,1,2 -> lane bits 2,1,0 | wires 3..6 -> pack bits 8,4,2,1 | wire 7 -> half.

template<int CS>
__device__ __forceinline__ void gate_shfl(ull R[16], ull I[16], unsigned lane, const GateSplats* gp) {
    const ulonglong2* q = reinterpret_cast<const ulonglong2*>(gp);
    ulonglong2 q0 = q[0], q1 = q[1], q2 = q[2], q3 = q[3];
    ull u00r = q0.x, u00i = q0.y, nu00i = q1.x, u01r = q1.y;
    ull nu01r = q2.x, u01i = q2.y, nu01i = q3.x;
    bool bit = (lane >> CS) & 1;
    ull CMr  = u00r;
    ull CMi  = bit ? nu00i : u00i;
    ull nCMi = bit ? u00i  : nu00i;
    ull COr  = bit ? nu01r : u01r;
    ull COi  = u01i, nCOi = nu01i;
    #pragma unroll
    for (int j = 0; j < 16; j++) {
        ull oR = shx64(R[j], 1 << CS), oI = shx64(I[j], 1 << CS);
        ull sR = R[j], sI = I[j];
        R[j] = f2fma(CMr, sR, f2fma(nCMi, sI, f2fma(COr, oR, f2mul(nCOi, oI))));
        I[j] = f2fma(CMr, sI, f2fma(CMi, sR, f2fma(COr, oI, f2mul(COi, oR))));
    }
}

template<int PM>
__device__ __forceinline__ void gate_cross(ull R[16], ull I[16], const GateSplats* gp) {
    const ulonglong2* q = reinterpret_cast<const ulonglong2*>(gp);
    ulonglong2 q0 = q[0], q1 = q[1], q2 = q[2], q3 = q[3];
    ull u00r = q0.x, u00i = q0.y, nu00i = q1.x, u01r = q1.y;
    ull nu01r = q2.x, u01i = q2.y, nu01i = q3.x;
    #pragma unroll
    for (int j = 0; j < 16; j++) {
        if (!(j & PM)) {
            ull aR = R[j], aI = I[j], bR = R[j | PM], bI = I[j | PM];
            R[j]      = f2fma(u00r,  aR, f2fma(nu00i, aI, f2fma(u01r, bR, f2mul(nu01i, bI))));
            I[j]      = f2fma(u00r,  aI, f2fma(u00i,  aR, f2fma(u01r, bI, f2mul(u01i,  bR))));
            R[j | PM] = f2fma(nu01r, aR, f2fma(nu01i, aI, f2fma(u00r, bR, f2mul(u00i,  bI))));
            I[j | PM] = f2fma(nu01r, aI, f2fma(u01i,  aR, f2fma(u00r, bI, f2mul(nu00i, bR))));
        }
    }
}

__device__ __forceinline__ void gate_v(ull R[16], ull I[16], const VSplats* vp) {
    const ulonglong2* q = reinterpret_cast<const ulonglong2*>(vp);
    ulonglong2 q0 = q[0], q1 = q[1], q2 = q[2];
    ull v00r = q0.x, v00i = q0.y, nv00i = q1.x, v01r = q1.y, v01i = q2.x, nv01i = q2.y;
    #pragma unroll
    for (int j = 0; j < 16; j++) {
        float2 fr = upk(R[j]), fi = upk(I[j]);
        ull aRe = spl(fr.x), bRe = spl(fr.y), aIm = spl(fi.x), bIm = spl(fi.y);
        R[j] = f2fma(v00r, aRe, f2fma(nv00i, aIm, f2fma(v01r, bRe, f2mul(nv01i, bIm))));
        I[j] = f2fma(v00r, aIm, f2fma(v00i,  aRe, f2fma(v01r, bIm, f2mul(v01i,  bRe))));
    }
}

template<int CS, int LM>
__device__ __forceinline__ void cnot_ll(ull R[16], ull I[16], unsigned lane) {
    bool cb = (lane >> CS) & 1;
    #pragma unroll
    for (int j = 0; j < 16; j++) {
        ull o = shx64(R[j], LM); R[j] = cb ? o : R[j];
        o = shx64(I[j], LM);     I[j] = cb ? o : I[j];
    }
}
template<int CS, int PM>
__device__ __forceinline__ void cnot_lp(ull R[16], ull I[16], unsigned lane) {
    bool cb = (lane >> CS) & 1;
    #pragma unroll
    for (int j = 0; j < 16; j++) {
        if (!(j & PM)) {
            ull a = R[j], b = R[j | PM];
            R[j] = cb ? b : a; R[j | PM] = cb ? a : b;
            a = I[j]; b = I[j | PM];
            I[j] = cb ? b : a; I[j | PM] = cb ? a : b;
        }
    }
}
template<int PM>
__device__ __forceinline__ void cnot_ph(ull R[16], ull I[16]) {
    #pragma unroll
    for (int j = 0; j < 16; j++) {
        if (j & PM) {
            float2 r = upk(R[j]); R[j] = pk(r.y, r.x);
            float2 i = upk(I[j]); I[j] = pk(i.y, i.x);
        }
    }
}
template<int PM, int LM>
__device__ __forceinline__ void cnot_pl(ull R[16], ull I[16]) {
    #pragma unroll
    for (int j = 0; j < 16; j++) {
        if (j & PM) { R[j] = shx64(R[j], LM); I[j] = shx64(I[j], LM); }
    }
}
template<int LM>
__device__ __forceinline__ void cnot_hl(ull R[16], ull I[16]) {
    #pragma unroll
    for (int j = 0; j < 16; j++) {
        float2 r = upk(R[j]);
        r.y = __shfl_xor_sync(0xffffffffu, r.y, LM);
        R[j] = pk(r.x, r.y);
        float2 i = upk(I[j]);
        i.y = __shfl_xor_sync(0xffffffffu, i.y, LM);
        I[j] = pk(i.x, i.y);
    }
}

#define SWAPJ(a, b) { ull t_ = R[a]; R[a] = R[b]; R[b] = t_; t_ = I[a]; I[a] = I[b]; I[b] = t_; }

__global__ __launch_bounds__(256, 2) void qlayer_kernel(
    const float* __restrict__ x,
    const float* __restrict__ W,
    const float* __restrict__ bvec,
    const float* __restrict__ scale,
    const float* __restrict__ bias,
    const float* __restrict__ qw,
    float* __restrict__ out)
{
    __shared__ float sW[8][512];          // 16 KB
    __shared__ GateSplats sSp[2][8];
    __shared__ VSplats sV[2];
    __shared__ float2 sG0[8][4];
    __shared__ uint4 sPv[16];             // 256 perm bytes, uint4-aligned
    __shared__ float sPar[24];            // bvec | scale | bias

    const int tid = threadIdx.x;

    for (int i = tid; i < 1024; i += 256)
        ((float4*)sW)[i] = ((const float4*)W)[i];

    if (tid < 24) {
        sPar[tid] = (tid < 8) ? bvec[tid] : (tid < 16) ? scale[tid - 8] : bias[tid - 16];
        int l = tid >> 3, w = tid & 7;
        const float* qp = qw + (l * 8 + w) * 3;
        float phi = qp[0], th = qp[1], om = qp[2];
        float ct, st_; sincosf(0.5f * th, &st_, &ct);
        float c0, s0, c1, s1;
        sincosf(0.5f * (phi + om), &s0, &c0);
        sincosf(0.5f * (phi - om), &s1, &c1);
        float2 u00 = make_float2(ct * c0, -ct * s0);
        float2 u01 = make_float2(-st_ * c1, -st_ * s1);
        if (l == 0) {
            sG0[w][0] = u00;
            sG0[w][1] = u01;
            sG0[w][2] = make_float2(st_ * c1, -st_ * s1);  // u10
            sG0[w][3] = make_float2(ct * c0, ct * s0);     // u11
        } else {
            GateSplats& g = sSp[l - 1][w];
            g.u00r = spl(u00.x); g.u00i = spl(u00.y); g.nu00i = spl(-u00.y);
            g.u01r = spl(u01.x); g.nu01r = spl(-u01.x);
            g.u01i = spl(u01.y); g.nu01i = spl(-u01.y);
            g.pad = 0;
            if (w == 7) {
                float2 u10 = make_float2(-u01.x, u01.y);
                float2 u11 = make_float2(u00.x, -u00.y);
                VSplats& v = sV[l - 1];
                v.v00r = pk(u00.x, u10.x); v.v00i = pk(u00.y, u10.y); v.nv00i = pk(-u00.y, -u10.y);
                v.v01r = pk(u01.x, u11.x); v.v01i = pk(u01.y, u11.y); v.nv01i = pk(-u01.y, -u11.y);
                v.p0 = 0; v.p1 = 0;
            }
        }
    }
    {
        int j = tid;
        #pragma unroll
        for (int w = 0; w < 8; w++) {
            int c = 7 - w, t = 7 - ((w + 3) & 7);
            if ((j >> c) & 1) j ^= (1 << t);
        }
        ((unsigned char*)sPv)[tid] = (unsigned char)j;
    }
    __syncthreads();

    const unsigned lane = tid & 31;
    const unsigned o = lane & 7;
    const int b = blockIdx.x * 32 + (tid >> 5) * 4 + (lane >> 3);

    // ---- projection ----
    float acc[8];
    #pragma unroll
    for (int w = 0; w < 8; w++) acc[w] = 0.f;
    const float4* xr = (const float4*)(x + (size_t)b * INDIM);
    #pragma unroll
    for (int c = 0; c < 16; c++) {
        float4 xv = xr[(c << 3) + o];
        #pragma unroll
        for (int w = 0; w < 8; w++) {
            float4 wv = ((const float4*)(sW[w]))[(c << 3) + o];
            acc[w] += xv.x * wv.x + xv.y * wv.y + xv.z * wv.z + xv.w * wv.w;
        }
    }
    {
        ull pa[4];
        #pragma unroll
        for (int t = 0; t < 4; t++) pa[t] = pk(acc[2 * t], acc[2 * t + 1]);
        #pragma unroll
        for (int off = 4; off > 0; off >>= 1) {
            #pragma unroll
            for (int t = 0; t < 4; t++) pa[t] = f2add(pa[t], shx64(pa[t], off));
        }
        #pragma unroll
        for (int t = 0; t < 4; t++) { float2 f = upk(pa[t]); acc[2 * t] = f.x; acc[2 * t + 1] = f.y; }
    }

    // ---- angles + fold layer-0 Rot ----
    float2 wa[8], wb[8];
    #pragma unroll
    for (int w = 0; w < 8; w++) {
        float t = (acc[w] + sPar[w]) * sPar[8 + w] + sPar[16 + w];
        float sg = 1.f / (1.f + __expf(-t));
        float cc, ss;
        __sincosf(sg * (0.5f * PI_F), &ss, &cc);
        float2 g00 = sG0[w][0], g01 = sG0[w][1];
        float2 g10 = sG0[w][2], g11 = sG0[w][3];
        wa[w] = make_float2(fmaf(g00.x, cc, g01.x * ss), fmaf(g00.y, cc, g01.y * ss));
        wb[w] = make_float2(fmaf(g10.x, cc, g11.x * ss), fmaf(g10.y, cc, g11.y * ss));
    }

    // ---- build product state ----
    float2 A = (o & 4) ? wb[0] : wa[0];
    A = cmul(A, (o & 2) ? wb[1] : wa[1]);
    A = cmul(A, (o & 1) ? wb[2] : wa[2]);

    float2 t3a = cmul(A, wa[3]), t3b = cmul(A, wb[3]);
    float2 t4[4];
    t4[0] = cmul(t3a, wa[4]); t4[1] = cmul(t3a, wb[4]);
    t4[2] = cmul(t3b, wa[4]); t4[3] = cmul(t3b, wb[4]);
    float2 t5[8];
    #pragma unroll
    for (int k = 0; k < 8; k++) t5[k] = cmul(t4[k >> 1], (k & 1) ? wb[5] : wa[5]);

    ull W7r  = pk(wa[7].x, wb[7].x);
    ull W7i  = pk(wa[7].y, wb[7].y);
    ull nW7i = pk(-wa[7].y, -wb[7].y);

    ull R[16], I[16];
    #pragma unroll
    for (int j = 0; j < 16; j++) {
        float2 C = cmul(t5[j >> 1], (j & 1) ? wb[6] : wa[6]);
        ull Cre = spl(C.x), Cim = spl(C.y);
        R[j] = f2fma(Cre, W7r, f2mul(Cim, nW7i));
        I[j] = f2fma(Cre, W7i, f2mul(Cim, W7r));
    }

    // ---- CNOT ring r=1: (7,6)(6,5)(5,4)(4,3)(3,2)(2,1)(1,0)(0,7) ----
    cnot_ll<2, 2>(R, I, lane);
    cnot_ll<1, 1>(R, I, lane);
    cnot_lp<0, 8>(R, I, lane);
    SWAPJ(8, 12); SWAPJ(9, 13); SWAPJ(10, 14); SWAPJ(11, 15);
    SWAPJ(4, 6);  SWAPJ(5, 7);  SWAPJ(12, 14); SWAPJ(13, 15);
    SWAPJ(2, 3);  SWAPJ(6, 7);  SWAPJ(10, 11); SWAPJ(14, 15);
    cnot_ph<1>(R, I);
    cnot_hl<4>(R, I);

    // ---- layer-1 Rots ----
    gate_shfl<2>(R, I, lane, &sSp[0][0]);
    gate_shfl<1>(R, I, lane, &sSp[0][1]);
    gate_shfl<0>(R, I, lane, &sSp[0][2]);
    gate_cross<8>(R, I, &sSp[0][3]);
    gate_cross<4>(R, I, &sSp[0][4]);
    gate_cross<2>(R, I, &sSp[0][5]);
    gate_cross<1>(R, I, &sSp[0][6]);
    gate_v(R, I, &sV[0]);

    // ---- CNOT ring r=2: (7,5)(6,4)(5,3)(4,2)(3,1)(2,0)(1,7)(0,6) ----
    cnot_ll<2, 1>(R, I, lane);
    cnot_lp<1, 8>(R, I, lane);
    cnot_lp<0, 4>(R, I, lane);
    SWAPJ(8, 10); SWAPJ(9, 11); SWAPJ(12, 14); SWAPJ(13, 15);
    SWAPJ(4, 5);  SWAPJ(6, 7);  SWAPJ(12, 13); SWAPJ(14, 15);
    cnot_ph<2>(R, I);
    cnot_pl<1, 4>(R, I);
    cnot_hl<2>(R, I);

    // ---- layer-2 Rots ----
    gate_shfl<2>(R, I, lane, &sSp[1][0]);
    gate_shfl<1>(R, I, lane, &sSp[1][1]);
    gate_shfl<0>(R, I, lane, &sSp[1][2]);
    gate_cross<8>(R, I, &sSp[1][3]);
    gate_cross<4>(R, I, &sSp[1][4]);
    gate_cross<2>(R, I, &sSp[1][5]);
    gate_cross<1>(R, I, &sSp[1][6]);
    gate_v(R, I, &sV[1]);

    // ---- measurement: sP(i^1)=sP(i)^0x21 -> halves share signs except wires 2,7 ----
    uint4 q0 = sPv[o << 1];
    uint4 q1 = sPv[(o << 1) | 1];
    unsigned su[8] = {q0.x, q0.y, q0.z, q0.w, q1.x, q1.y, q1.z, q1.w};

    float zs[8];
    #pragma unroll
    for (int w = 0; w < 8; w++) zs[w] = 0.f;
    #pragma unroll
    for (int j = 0; j < 16; j++) {
        ull P = f2fma(R[j], R[j], f2mul(I[j], I[j]));
        float2 pp = upk(P);
        float sum = pp.x + pp.y;
        float dif = pp.x - pp.y;
        // even-amp byte offset = j*2 -> uint j>>1, byte (j&1)*2 -> shift (j&1)*16
        unsigned s8 = (su[j >> 1] >> ((j & 1) * 16)) & 0xffu;
        #pragma unroll
        for (int w = 0; w < 8; w++) {
            float val = (w == 2 || w == 7) ? dif : sum;
            unsigned sm = (s8 << (24 + w)) & 0x80000000u;
            zs[w] += __int_as_float(__float_as_int(val) ^ sm);
        }
    }

    ull zp[4];
    #pragma unroll
    for (int t = 0; t < 4; t++) zp[t] = pk(zs[2 * t], zs[2 * t + 1]);
    #pragma unroll
    for (int off = 4; off > 0; off >>= 1) {
        #pragma unroll
        for (int t = 0; t < 4; t++) zp[t] = f2add(zp[t], shx64(zp[t], off));
    }
    float2 z01 = upk(zp[0]), z23 = upk(zp[1]), z45 = upk(zp[2]), z67 = upk(zp[3]);
    float v = z01.x;
    if (o == 1) v = z01.y;
    if (o == 2) v = z23.x;
    if (o == 3) v = z23.y;
    if (o == 4) v = z45.x;
    if (o == 5) v = z45.y;
    if (o == 6) v = z67.x;
    if (o == 7) v = z67.y;
    out[(size_t)b * 8 + o] = v;
}

extern "C" void kernel_launch(void* const* d_in, const int* in_sizes, int n_in,
                              void* d_out, int out_size) {
    const float* x     = (const float*)d_in[0];
    const float* W     = (const float*)d_in[1];
    const float* bvec  = (const float*)d_in[2];
    const float* scale = (const float*)d_in[3];
    const float* bias  = (const float*)d_in[4];
    const float* qw    = (const float*)d_in[5];
    float* out = (float*)d_out;
    qlayer_kernel<<<BATCHN / 32, 256>>>(x, W, bvec, scale, bias, qw, out);
}